// round 1
// baseline (speedup 1.0000x reference)
#include <cuda_runtime.h>
#include <cuda_bf16.h>
#include <math.h>

// ---------------- problem constants ----------------
#define BATCH 128
#define SEQ   50          // S = SL/HZ = 5000/100
#define DMODEL 1024
#define DFF   4096
#define NHEAD 16
#define DK    64
#define NLAYER 5
#define KEMB  1200        // CH*HZ
#define NTOK  (BATCH*SEQ) // 6400
#define NCLS  71

// ---------------- scratch (device globals; no allocation allowed) ----------------
__device__ float d_h [NTOK * DMODEL];
__device__ float d_a [NTOK * DMODEL];
__device__ float d_q [NTOK * DMODEL];
__device__ float d_k [NTOK * DMODEL];
__device__ float d_v [NTOK * DMODEL];
__device__ float d_o [NTOK * DMODEL];
__device__ float d_ff[NTOK * DFF];
__device__ float d_z0[BATCH * DMODEL];
__device__ float d_z1[BATCH * DMODEL];

// ---------------- SGEMM: C(MxN) = A(MxK) @ B(KxN) + epilogue ----------------
// requires M%128==0, N%128==0, K%8==0 (true for all call sites)
// epi: 0 = +bias, 1 = relu(+bias), 2 = resid + (+bias), 3 = + positional encoding
#define BM 128
#define BN 128
#define BK 8
#define TM 8
#define TN 8

__global__ void __launch_bounds__(256) sgemm_kernel(
    const float* __restrict__ A, const float* __restrict__ B,
    const float* __restrict__ bias, const float* __restrict__ resid,
    float* __restrict__ C, int M, int N, int K, int epi)
{
    __shared__ float As[BK][BM];
    __shared__ float Bs[BK][BN];

    const int tid = threadIdx.x;
    const int m0 = blockIdx.y * BM;
    const int n0 = blockIdx.x * BN;

    const int arow = tid >> 1;          // 0..127
    const int acol = (tid & 1) * 4;     // 0 or 4
    const int brow = tid >> 5;          // 0..7
    const int bcol = (tid & 31) * 4;    // 0..124

    const float* Aptr = A + (size_t)(m0 + arow) * K + acol;
    const float* Bptr = B + (size_t)brow * N + n0 + bcol;

    const int tx = tid & 15;
    const int ty = tid >> 4;

    float acc[TM][TN];
#pragma unroll
    for (int i = 0; i < TM; i++)
#pragma unroll
        for (int j = 0; j < TN; j++) acc[i][j] = 0.f;

    for (int k0 = 0; k0 < K; k0 += BK) {
        float4 a4 = *reinterpret_cast<const float4*>(Aptr + k0);
        float4 b4 = *reinterpret_cast<const float4*>(Bptr + (size_t)k0 * N);
        As[acol + 0][arow] = a4.x;
        As[acol + 1][arow] = a4.y;
        As[acol + 2][arow] = a4.z;
        As[acol + 3][arow] = a4.w;
        *reinterpret_cast<float4*>(&Bs[brow][bcol]) = b4;
        __syncthreads();

#pragma unroll
        for (int k = 0; k < BK; k++) {
            float ra[TM], rb[TN];
            *reinterpret_cast<float4*>(&ra[0]) = *reinterpret_cast<const float4*>(&As[k][ty * TM]);
            *reinterpret_cast<float4*>(&ra[4]) = *reinterpret_cast<const float4*>(&As[k][ty * TM + 4]);
            *reinterpret_cast<float4*>(&rb[0]) = *reinterpret_cast<const float4*>(&Bs[k][tx * TN]);
            *reinterpret_cast<float4*>(&rb[4]) = *reinterpret_cast<const float4*>(&Bs[k][tx * TN + 4]);
#pragma unroll
            for (int i = 0; i < TM; i++)
#pragma unroll
                for (int j = 0; j < TN; j++)
                    acc[i][j] = fmaf(ra[i], rb[j], acc[i][j]);
        }
        __syncthreads();
    }

#pragma unroll
    for (int i = 0; i < TM; i++) {
        const int row = m0 + ty * TM + i;
        const size_t base = (size_t)row * N + n0 + tx * TN;
#pragma unroll
        for (int j = 0; j < TN; j++) {
            const int col = n0 + tx * TN + j;
            float v = acc[i][j];
            if (bias) v += __ldg(&bias[col]);
            if (epi == 1) {
                v = fmaxf(v, 0.f);
            } else if (epi == 2) {
                v += resid[base + j];
            } else if (epi == 3) {
                const int srow = row % SEQ;
                const int c2 = col & ~1;
                float dv = expf((float)c2 * (-9.210340371976184f / (float)DMODEL));
                float ang = (float)srow * dv;
                float sn, cs;
                sincosf(ang, &sn, &cs);
                v += (col & 1) ? cs : sn;
            }
            C[base + j] = v;
        }
    }
}

// ---------------- LayerNorm (ddof=1, eps added to std) ----------------
__global__ void __launch_bounds__(256) ln_kernel(
    const float* __restrict__ in, const float* __restrict__ g,
    const float* __restrict__ b, float* __restrict__ out)
{
    const int row = blockIdx.x;
    const float* x = in + (size_t)row * DMODEL;
    float vals[4];
    float s = 0.f, s2 = 0.f;
#pragma unroll
    for (int i = 0; i < 4; i++) {
        float v = x[threadIdx.x + i * 256];
        vals[i] = v;
        s += v;
        s2 += v * v;
    }
#pragma unroll
    for (int o = 16; o; o >>= 1) {
        s  += __shfl_xor_sync(0xffffffffu, s, o);
        s2 += __shfl_xor_sync(0xffffffffu, s2, o);
    }
    __shared__ float sh[2][8];
    const int w = threadIdx.x >> 5;
    if ((threadIdx.x & 31) == 0) { sh[0][w] = s; sh[1][w] = s2; }
    __syncthreads();
    if (threadIdx.x < 32) {
        s  = (threadIdx.x < 8) ? sh[0][threadIdx.x] : 0.f;
        s2 = (threadIdx.x < 8) ? sh[1][threadIdx.x] : 0.f;
#pragma unroll
        for (int o = 4; o; o >>= 1) {
            s  += __shfl_xor_sync(0xffffffffu, s, o);
            s2 += __shfl_xor_sync(0xffffffffu, s2, o);
        }
        if (threadIdx.x == 0) { sh[0][0] = s; sh[1][0] = s2; }
    }
    __syncthreads();
    const float mean = sh[0][0] * (1.f / (float)DMODEL);
    float var = (sh[1][0] - (float)DMODEL * mean * mean) * (1.f / (float)(DMODEL - 1));
    var = fmaxf(var, 0.f);
    const float inv = 1.f / (sqrtf(var) + 1e-6f);
#pragma unroll
    for (int i = 0; i < 4; i++) {
        const int c = threadIdx.x + i * 256;
        out[(size_t)row * DMODEL + c] = g[c] * (vals[i] - mean) * inv + b[c];
    }
}

// ---------------- attention: one block per (b, h) ----------------
__global__ void __launch_bounds__(256) attn_kernel(
    const float* __restrict__ Q, const float* __restrict__ K,
    const float* __restrict__ V, float* __restrict__ O)
{
    const int bh = blockIdx.x;
    const int b = bh >> 4;
    const int h = bh & 15;

    __shared__ float qs[SEQ][DK];        // broadcast access: no pad needed
    __shared__ float ks[SEQ][DK + 1];    // padded: accessed across rows
    __shared__ float vs[SEQ][DK];        // accessed along d: no pad
    __shared__ float sc[SEQ][SEQ];

    const int tid = threadIdx.x;

    for (int e = tid; e < SEQ * DK; e += 256) {
        const int s = e >> 6;
        const int d = e & 63;
        const size_t gidx = (size_t)(b * SEQ + s) * DMODEL + h * DK + d;
        qs[s][d] = Q[gidx];
        ks[s][d] = K[gidx];
        vs[s][d] = V[gidx];
    }
    __syncthreads();

    for (int e = tid; e < SEQ * SEQ; e += 256) {
        const int i = e / SEQ;
        const int j = e % SEQ;
        float acc = 0.f;
#pragma unroll
        for (int d = 0; d < DK; d++) acc = fmaf(qs[i][d], ks[j][d], acc);
        sc[i][j] = acc * 0.125f;   // 1/sqrt(64)
    }
    __syncthreads();

    if (tid < SEQ) {
        float mx = -1e30f;
#pragma unroll 1
        for (int j = 0; j < SEQ; j++) mx = fmaxf(mx, sc[tid][j]);
        float sum = 0.f;
#pragma unroll 1
        for (int j = 0; j < SEQ; j++) {
            float ev = expf(sc[tid][j] - mx);
            sum += ev;
            sc[tid][j] = ev;
        }
        const float r = 1.f / sum;
#pragma unroll 1
        for (int j = 0; j < SEQ; j++) sc[tid][j] *= r;
    }
    __syncthreads();

    for (int e = tid; e < SEQ * DK; e += 256) {
        const int i = e >> 6;
        const int d = e & 63;
        float acc = 0.f;
#pragma unroll
        for (int j = 0; j < SEQ; j++) acc = fmaf(sc[i][j], vs[j][d], acc);
        O[(size_t)(b * SEQ + i) * DMODEL + h * DK + d] = acc;
    }
}

// ---------------- pooled row: final LN + first batchnorm-ish scale ----------------
__global__ void __launch_bounds__(256) pool_ln_scale_kernel(
    const float* __restrict__ hbuf,
    const float* __restrict__ fin_g, const float* __restrict__ fin_b,
    const float* __restrict__ bn_g, const float* __restrict__ bn_b,
    float* __restrict__ z)
{
    const int bb = blockIdx.x;
    const float* x = hbuf + (size_t)(bb * SEQ + (SEQ - 1)) * DMODEL;
    float vals[4];
    float s = 0.f, s2 = 0.f;
#pragma unroll
    for (int i = 0; i < 4; i++) {
        float v = x[threadIdx.x + i * 256];
        vals[i] = v;
        s += v;
        s2 += v * v;
    }
#pragma unroll
    for (int o = 16; o; o >>= 1) {
        s  += __shfl_xor_sync(0xffffffffu, s, o);
        s2 += __shfl_xor_sync(0xffffffffu, s2, o);
    }
    __shared__ float sh[2][8];
    const int w = threadIdx.x >> 5;
    if ((threadIdx.x & 31) == 0) { sh[0][w] = s; sh[1][w] = s2; }
    __syncthreads();
    if (threadIdx.x < 32) {
        s  = (threadIdx.x < 8) ? sh[0][threadIdx.x] : 0.f;
        s2 = (threadIdx.x < 8) ? sh[1][threadIdx.x] : 0.f;
#pragma unroll
        for (int o = 4; o; o >>= 1) {
            s  += __shfl_xor_sync(0xffffffffu, s, o);
            s2 += __shfl_xor_sync(0xffffffffu, s2, o);
        }
        if (threadIdx.x == 0) { sh[0][0] = s; sh[1][0] = s2; }
    }
    __syncthreads();
    const float mean = sh[0][0] * (1.f / (float)DMODEL);
    float var = (sh[1][0] - (float)DMODEL * mean * mean) * (1.f / (float)(DMODEL - 1));
    var = fmaxf(var, 0.f);
    const float inv = 1.f / (sqrtf(var) + 1e-6f);
    const float invbn = 1.f / sqrtf(1.0f + 1e-5f);
#pragma unroll
    for (int i = 0; i < 4; i++) {
        const int c = threadIdx.x + i * 256;
        const float lnv = fin_g[c] * (vals[i] - mean) * inv + fin_b[c];
        z[(size_t)bb * DMODEL + c] = lnv * invbn * bn_g[c] + bn_b[c];
    }
}

// ---------------- second bn scale (on relu'd classifier features) ----------------
__global__ void __launch_bounds__(256) bn2_kernel(
    const float* __restrict__ in, const float* __restrict__ g,
    const float* __restrict__ b, float* __restrict__ out)
{
    const int idx = blockIdx.x * 256 + threadIdx.x;   // < 128*1024
    const int c = idx & (DMODEL - 1);
    const float invbn = 1.f / sqrtf(1.0f + 1e-5f);
    out[idx] = in[idx] * invbn * g[c] + b[c];
}

// ---------------- final 128x71 classifier ----------------
__global__ void __launch_bounds__(128) fc_kernel(
    const float* __restrict__ z, const float* __restrict__ W,
    const float* __restrict__ bias, float* __restrict__ out)
{
    __shared__ float zs[DMODEL];
    const int bb = blockIdx.x;
    for (int i = threadIdx.x; i < DMODEL; i += 128) zs[i] = z[(size_t)bb * DMODEL + i];
    __syncthreads();
    const int c = threadIdx.x;
    if (c < NCLS) {
        float acc = bias[c];
        for (int k = 0; k < DMODEL; k++) acc = fmaf(zs[k], W[(size_t)k * NCLS + c], acc);
        out[(size_t)bb * NCLS + c] = acc;
    }
}

// ---------------- host launcher ----------------
static inline void launch_gemm(const float* A, const float* B, const float* bias,
                               const float* resid, float* C, int M, int N, int K, int epi)
{
    dim3 grid(N / BN, M / BM);
    sgemm_kernel<<<grid, 256>>>(A, B, bias, resid, C, M, N, K, epi);
}

extern "C" void kernel_launch(void* const* d_in, const int* in_sizes, int n_in,
                              void* d_out, int out_size)
{
    const float* x        = (const float*)d_in[0];
    const float* embed_w  = (const float*)d_in[1];
    const float* attn_w   = (const float*)d_in[2];
    const float* attn_b   = (const float*)d_in[3];
    const float* ff_w1    = (const float*)d_in[4];
    const float* ff_b1    = (const float*)d_in[5];
    const float* ff_w2    = (const float*)d_in[6];
    const float* ff_b2    = (const float*)d_in[7];
    const float* ln_g     = (const float*)d_in[8];
    const float* ln_b     = (const float*)d_in[9];
    const float* fin_g    = (const float*)d_in[10];
    const float* fin_b    = (const float*)d_in[11];
    const float* cf_bn_g  = (const float*)d_in[12];
    const float* cf_bn_b  = (const float*)d_in[13];
    const float* cf_w     = (const float*)d_in[14];
    const float* cf_b     = (const float*)d_in[15];
    const float* fc_bn_g  = (const float*)d_in[16];
    const float* fc_bn_b  = (const float*)d_in[17];
    const float* fc_w     = (const float*)d_in[18];
    const float* fc_b     = (const float*)d_in[19];

    float *g_h, *g_a, *g_q, *g_k, *g_v, *g_o, *g_ff, *g_z0, *g_z1;
    cudaGetSymbolAddress((void**)&g_h,  d_h);
    cudaGetSymbolAddress((void**)&g_a,  d_a);
    cudaGetSymbolAddress((void**)&g_q,  d_q);
    cudaGetSymbolAddress((void**)&g_k,  d_k);
    cudaGetSymbolAddress((void**)&g_v,  d_v);
    cudaGetSymbolAddress((void**)&g_o,  d_o);
    cudaGetSymbolAddress((void**)&g_ff, d_ff);
    cudaGetSymbolAddress((void**)&g_z0, d_z0);
    cudaGetSymbolAddress((void**)&g_z1, d_z1);

    // embed: h = X(6400x1200) @ embed_w(1200x1024) + positional encoding
    launch_gemm(x, embed_w, nullptr, nullptr, g_h, NTOK, DMODEL, KEMB, 3);

    for (int l = 0; l < NLAYER; l++) {
        const float* w  = attn_w + (size_t)l * 4 * DMODEL * DMODEL;
        const float* bq = attn_b + (size_t)l * 4 * DMODEL;

        // LN1
        ln_kernel<<<NTOK, 256>>>(g_h, ln_g + (size_t)(l * 2) * DMODEL,
                                 ln_b + (size_t)(l * 2) * DMODEL, g_a);
        // QKV
        launch_gemm(g_a, w + 0 * (size_t)DMODEL * DMODEL, bq + 0 * DMODEL, nullptr, g_q, NTOK, DMODEL, DMODEL, 0);
        launch_gemm(g_a, w + 1 * (size_t)DMODEL * DMODEL, bq + 1 * DMODEL, nullptr, g_k, NTOK, DMODEL, DMODEL, 0);
        launch_gemm(g_a, w + 2 * (size_t)DMODEL * DMODEL, bq + 2 * DMODEL, nullptr, g_v, NTOK, DMODEL, DMODEL, 0);
        // attention
        attn_kernel<<<BATCH * NHEAD, 256>>>(g_q, g_k, g_v, g_o);
        // h += o @ Wo + bo
        launch_gemm(g_o, w + 3 * (size_t)DMODEL * DMODEL, bq + 3 * DMODEL, g_h, g_h, NTOK, DMODEL, DMODEL, 2);
        // LN2
        ln_kernel<<<NTOK, 256>>>(g_h, ln_g + (size_t)(l * 2 + 1) * DMODEL,
                                 ln_b + (size_t)(l * 2 + 1) * DMODEL, g_a);
        // FF
        launch_gemm(g_a, ff_w1 + (size_t)l * DMODEL * DFF, ff_b1 + (size_t)l * DFF, nullptr, g_ff, NTOK, DFF, DMODEL, 1);
        launch_gemm(g_ff, ff_w2 + (size_t)l * DFF * DMODEL, ff_b2 + (size_t)l * DMODEL, g_h, g_h, NTOK, DMODEL, DFF, 2);
    }

    // classifier head
    pool_ln_scale_kernel<<<BATCH, 256>>>(g_h, fin_g, fin_b, cf_bn_g, cf_bn_b, g_z0);
    launch_gemm(g_z0, cf_w, cf_b, nullptr, g_z1, BATCH, DMODEL, DMODEL, 1);
    bn2_kernel<<<(BATCH * DMODEL) / 256, 256>>>(g_z1, fc_bn_g, fc_bn_b, g_z0);
    fc_kernel<<<BATCH, 128>>>(g_z0, fc_w, fc_b, (float*)d_out);
}

// round 3
// speedup vs baseline: 2.9698x; 2.9698x over previous
#include <cuda_runtime.h>
#include <cuda_fp16.h>
#include <math.h>
#include <stdint.h>

// ---------------- problem constants ----------------
#define BATCH 128
#define SEQ   50
#define DMODEL 1024
#define DFF   4096
#define NHEAD 16
#define DK    64
#define NLAYER 5
#define KEMB  1200
#define KEMBP 1216          // padded to multiple of 32
#define NTOK  6400
#define NCLS  71

// ---------------- HMMA GEMM tile config ----------------
#define GBM 128
#define GBN 128
#define GBK 32
#define OFF_AH 0
#define OFF_AL 8192
#define OFF_BH 16384
#define OFF_BL 24576
#define STAGE_BYTES 32768
#define TG_SMEM 65536

// ---------------- weight scratch layout (transposed fp16 hi/lo) ----------------
#define WT_EMB_SZ (1024u*1216u)
#define WT_LAYER  (12u*1024u*1024u)           // q,k,v,o + ff1T + ff2T
#define WT_TOTAL  (WT_EMB_SZ + 5u*WT_LAYER)

// ---------------- scratch (device globals) ----------------
__device__ float d_h [NTOK * DMODEL];
__device__ float d_q [NTOK * DMODEL];
__device__ float d_k [NTOK * DMODEL];
__device__ float d_v [NTOK * DMODEL];
__device__ float d_z0[BATCH * DMODEL];
__device__ float d_z1[BATCH * DMODEL];

__device__ __align__(16) __half d_xh[NTOK * KEMBP];
__device__ __align__(16) __half d_xl[NTOK * KEMBP];
__device__ __align__(16) __half d_ah[NTOK * DMODEL];
__device__ __align__(16) __half d_al[NTOK * DMODEL];
__device__ __align__(16) __half d_oh[NTOK * DMODEL];
__device__ __align__(16) __half d_ol[NTOK * DMODEL];
__device__ __align__(16) __half d_fh[NTOK * DFF];
__device__ __align__(16) __half d_fl[NTOK * DFF];
__device__ __align__(16) __half d_wth[WT_TOTAL];
__device__ __align__(16) __half d_wtl[WT_TOTAL];

// ---------------- PTX helpers ----------------
__device__ __forceinline__ uint32_t smem_u32(const void* p) {
    uint32_t a;
    asm("{ .reg .u64 t; cvta.to.shared.u64 t, %1; cvt.u32.u64 %0, t; }" : "=r"(a) : "l"(p));
    return a;
}
__device__ __forceinline__ void cpa16(uint32_t dst, const void* src) {
    asm volatile("cp.async.cg.shared.global [%0], [%1], 16;" :: "r"(dst), "l"(src));
}
#define CP_COMMIT() asm volatile("cp.async.commit_group;" ::: "memory")
#define CP_WAIT1()  asm volatile("cp.async.wait_group 1;" ::: "memory")
#define CP_WAIT0()  asm volatile("cp.async.wait_group 0;" ::: "memory")
#define LDSM4(r, a) \
    asm volatile("ldmatrix.sync.aligned.m8n8.x4.shared.b16 {%0,%1,%2,%3}, [%4];" \
        : "=r"((r)[0]), "=r"((r)[1]), "=r"((r)[2]), "=r"((r)[3]) : "r"(a))
#define MMA16816(c, a, b) \
    asm volatile("mma.sync.aligned.m16n8k16.row.col.f32.f16.f16.f32 " \
        "{%0,%1,%2,%3}, {%4,%5,%6,%7}, {%8,%9}, {%0,%1,%2,%3};" \
        : "+f"((c)[0]), "+f"((c)[1]), "+f"((c)[2]), "+f"((c)[3]) \
        : "r"((a)[0]), "r"((a)[1]), "r"((a)[2]), "r"((a)[3]), "r"((b)[0]), "r"((b)[1]))

__device__ __forceinline__ void split_f16(float v, __half& h, __half& l) {
    h = __float2half_rn(v);
    l = __float2half_rn(v - __half2float(h));
}

// ---------------- HMMA GEMM: C(MxN) = (Ah+Al) @ (Bh+Bl)^T, fp32 accum ----------------
// A: [M][Kp] fp16 hi/lo.  B: [N][Kp] fp16 hi/lo (weights pre-transposed).
// Kp%32==0, M%128==0, N%128==0.
// epi: 0 = +bias -> Cf; 1 = relu(+bias) -> Chi/Clo; 2 = +bias+resid -> Cf; 3 = +PE -> Cf
__global__ void __launch_bounds__(256) tgemm_kernel(
    const __half* __restrict__ Ah, const __half* __restrict__ Al,
    const __half* __restrict__ Bh, const __half* __restrict__ Bl,
    const float* __restrict__ bias, const float* __restrict__ resid,
    float* __restrict__ Cf, __half* __restrict__ Chi, __half* __restrict__ Clo,
    int Kp, int N, int epi)
{
    extern __shared__ char sm[];
    const uint32_t smb = smem_u32(sm);
    const int tid  = threadIdx.x;
    const int lane = tid & 31;
    const int wid  = tid >> 5;
    const int wm   = wid & 3;      // warp m block (32 rows)
    const int wn   = wid >> 2;     // warp n block (64 cols)
    const int m0 = blockIdx.y * GBM;
    const int n0 = blockIdx.x * GBN;

    float acc[2][8][4];
#pragma unroll
    for (int i = 0; i < 2; i++)
#pragma unroll
        for (int j = 0; j < 8; j++)
#pragma unroll
            for (int t = 0; t < 4; t++) acc[i][j][t] = 0.f;

    auto load_stage = [&](int st, int k0) {
        const uint32_t sb = smb + (uint32_t)st * STAGE_BYTES;
#pragma unroll
        for (int i = 0; i < 2; i++) {
            const int id = tid + i * 256;          // 0..511
            const int row = id >> 2, cc = id & 3;
            const uint32_t off = (uint32_t)((row << 6) + ((cc ^ ((row >> 1) & 3)) << 4));
            const size_t ka = (size_t)(m0 + row) * Kp + k0 + cc * 8;
            const size_t kb = (size_t)(n0 + row) * Kp + k0 + cc * 8;
            cpa16(sb + OFF_AH + off, Ah + ka);
            cpa16(sb + OFF_AL + off, Al + ka);
            cpa16(sb + OFF_BH + off, Bh + kb);
            cpa16(sb + OFF_BL + off, Bl + kb);
        }
    };

    auto compute = [&](int st) {
        const uint32_t sb = smb + (uint32_t)st * STAGE_BYTES;
#pragma unroll
        for (int ks = 0; ks < 2; ks++) {
            uint32_t aH[2][4], aL[2][4];
#pragma unroll
            for (int mt = 0; mt < 2; mt++) {
                const int r = wm * 32 + mt * 16 + (lane & 15);
                const int ch = ks * 2 + (lane >> 4);
                const uint32_t off = (uint32_t)((r << 6) + ((ch ^ ((r >> 1) & 3)) << 4));
                LDSM4(aH[mt], sb + OFF_AH + off);
                LDSM4(aL[mt], sb + OFF_AL + off);
            }
            uint32_t bH[8][2], bL[8][2];
#pragma unroll
            for (int p = 0; p < 4; p++) {
                const int r = wn * 64 + p * 16 + (lane & 7) + ((lane & 16) >> 1);
                const int ch = ks * 2 + ((lane >> 3) & 1);
                const uint32_t off = (uint32_t)((r << 6) + ((ch ^ ((r >> 1) & 3)) << 4));
                uint32_t q[4];
                LDSM4(q, sb + OFF_BH + off);
                bH[p*2][0] = q[0]; bH[p*2][1] = q[1];
                bH[p*2+1][0] = q[2]; bH[p*2+1][1] = q[3];
                LDSM4(q, sb + OFF_BL + off);
                bL[p*2][0] = q[0]; bL[p*2][1] = q[1];
                bL[p*2+1][0] = q[2]; bL[p*2+1][1] = q[3];
            }
            // three split terms, each accumulator revisited after 15 other MMAs
#pragma unroll
            for (int mt = 0; mt < 2; mt++)
#pragma unroll
                for (int nt = 0; nt < 8; nt++) MMA16816(acc[mt][nt], aH[mt], bH[nt]);
#pragma unroll
            for (int mt = 0; mt < 2; mt++)
#pragma unroll
                for (int nt = 0; nt < 8; nt++) MMA16816(acc[mt][nt], aH[mt], bL[nt]);
#pragma unroll
            for (int mt = 0; mt < 2; mt++)
#pragma unroll
                for (int nt = 0; nt < 8; nt++) MMA16816(acc[mt][nt], aL[mt], bH[nt]);
        }
    };

    const int nchunk = Kp / GBK;
    load_stage(0, 0);
    CP_COMMIT();
    for (int c = 0; c < nchunk; c++) {
        if (c + 1 < nchunk) {
            load_stage((c + 1) & 1, (c + 1) * GBK);
            CP_COMMIT();
            CP_WAIT1();
        } else {
            CP_WAIT0();
        }
        __syncthreads();
        compute(c & 1);
        __syncthreads();
    }

    // ---------------- epilogue ----------------
#pragma unroll
    for (int mt = 0; mt < 2; mt++) {
        const int r0 = m0 + wm * 32 + mt * 16 + (lane >> 2);
#pragma unroll
        for (int nt = 0; nt < 8; nt++) {
            const int col = n0 + wn * 64 + nt * 8 + (lane & 3) * 2;
            const float* a = acc[mt][nt];
            if (epi == 1) {
                const float b0 = __ldg(&bias[col]);
                const float b1 = __ldg(&bias[col + 1]);
#pragma unroll
                for (int rr = 0; rr < 2; rr++) {
                    const int row = r0 + rr * 8;
                    const float v0 = fmaxf(a[rr * 2 + 0] + b0, 0.f);
                    const float v1 = fmaxf(a[rr * 2 + 1] + b1, 0.f);
                    __half h0, l0, h1, l1;
                    split_f16(v0, h0, l0);
                    split_f16(v1, h1, l1);
                    *reinterpret_cast<__half2*>(&Chi[(size_t)row * N + col]) = __halves2half2(h0, h1);
                    *reinterpret_cast<__half2*>(&Clo[(size_t)row * N + col]) = __halves2half2(l0, l1);
                }
            } else if (epi == 3) {
                const float dv = expf((float)(col & ~1) * (-9.210340371976184f / (float)DMODEL));
#pragma unroll
                for (int rr = 0; rr < 2; rr++) {
                    const int row = r0 + rr * 8;
                    const int srow = row % SEQ;
                    float sn, cs;
                    sincosf((float)srow * dv, &sn, &cs);
                    float2 o;
                    o.x = a[rr * 2 + 0] + sn;   // even col -> sin
                    o.y = a[rr * 2 + 1] + cs;   // odd col  -> cos
                    *reinterpret_cast<float2*>(&Cf[(size_t)row * N + col]) = o;
                }
            } else {
                const float b0 = __ldg(&bias[col]);
                const float b1 = __ldg(&bias[col + 1]);
#pragma unroll
                for (int rr = 0; rr < 2; rr++) {
                    const int row = r0 + rr * 8;
                    float v0 = a[rr * 2 + 0] + b0;
                    float v1 = a[rr * 2 + 1] + b1;
                    if (epi == 2) {
                        const float2 rv = *reinterpret_cast<const float2*>(&resid[(size_t)row * N + col]);
                        v0 += rv.x; v1 += rv.y;
                    }
                    float2 o; o.x = v0; o.y = v1;
                    *reinterpret_cast<float2*>(&Cf[(size_t)row * N + col]) = o;
                }
            }
        }
    }
}

// ---------------- converters ----------------
__global__ void __launch_bounds__(256) cvt_x_kernel(
    const float* __restrict__ x, __half* __restrict__ xh, __half* __restrict__ xl)
{
    const int idx = blockIdx.x * 256 + threadIdx.x;
    if (idx >= NTOK * KEMBP) return;
    const int r = idx / KEMBP, c = idx % KEMBP;
    const float v = (c < KEMB) ? x[(size_t)r * KEMB + c] : 0.f;
    __half h, l; split_f16(v, h, l);
    xh[idx] = h; xl[idx] = l;
}

// W [K][N] fp32 -> transposed, split, padded: Th/Tl [N][Kp] fp16
__global__ void cvt_wT_kernel(
    const float* __restrict__ W, __half* __restrict__ Th, __half* __restrict__ Tl,
    int K, int N, int Kp)
{
    __shared__ float t[32][33];
    const int k0 = blockIdx.y * 32, n0 = blockIdx.x * 32;
    const int tx = threadIdx.x, ty = threadIdx.y;   // block (32, 8)
#pragma unroll
    for (int i = 0; i < 32; i += 8) {
        const int k = k0 + ty + i;
        t[ty + i][tx] = (k < K) ? W[(size_t)k * N + n0 + tx] : 0.f;
    }
    __syncthreads();
#pragma unroll
    for (int i = 0; i < 32; i += 8) {
        const int n = n0 + ty + i;
        const int k = k0 + tx;
        __half h, l; split_f16(t[tx][ty + i], h, l);
        Th[(size_t)n * Kp + k] = h;
        Tl[(size_t)n * Kp + k] = l;
    }
}

// ---------------- LayerNorm (ddof=1, eps on std) -> fp16 hi/lo ----------------
__global__ void __launch_bounds__(256) ln_kernel(
    const float* __restrict__ in, const float* __restrict__ g,
    const float* __restrict__ b, __half* __restrict__ outh, __half* __restrict__ outl)
{
    const int row = blockIdx.x;
    const float* x = in + (size_t)row * DMODEL;
    float vals[4];
    float s = 0.f, s2 = 0.f;
#pragma unroll
    for (int i = 0; i < 4; i++) {
        float v = x[threadIdx.x + i * 256];
        vals[i] = v; s += v; s2 += v * v;
    }
#pragma unroll
    for (int o = 16; o; o >>= 1) {
        s  += __shfl_xor_sync(0xffffffffu, s, o);
        s2 += __shfl_xor_sync(0xffffffffu, s2, o);
    }
    __shared__ float sh[2][8];
    const int w = threadIdx.x >> 5;
    if ((threadIdx.x & 31) == 0) { sh[0][w] = s; sh[1][w] = s2; }
    __syncthreads();
    if (threadIdx.x < 32) {
        s  = (threadIdx.x < 8) ? sh[0][threadIdx.x] : 0.f;
        s2 = (threadIdx.x < 8) ? sh[1][threadIdx.x] : 0.f;
#pragma unroll
        for (int o = 4; o; o >>= 1) {
            s  += __shfl_xor_sync(0xffffffffu, s, o);
            s2 += __shfl_xor_sync(0xffffffffu, s2, o);
        }
        if (threadIdx.x == 0) { sh[0][0] = s; sh[1][0] = s2; }
    }
    __syncthreads();
    const float mean = sh[0][0] * (1.f / (float)DMODEL);
    float var = (sh[1][0] - (float)DMODEL * mean * mean) * (1.f / (float)(DMODEL - 1));
    var = fmaxf(var, 0.f);
    const float inv = 1.f / (sqrtf(var) + 1e-6f);
#pragma unroll
    for (int i = 0; i < 4; i++) {
        const int c = threadIdx.x + i * 256;
        const float r = g[c] * (vals[i] - mean) * inv + b[c];
        __half h, l; split_f16(r, h, l);
        outh[(size_t)row * DMODEL + c] = h;
        outl[(size_t)row * DMODEL + c] = l;
    }
}

// ---------------- attention: one block per (b, h); fp16 hi/lo out ----------------
__global__ void __launch_bounds__(256) attn_kernel(
    const float* __restrict__ Q, const float* __restrict__ K,
    const float* __restrict__ V, __half* __restrict__ Oh, __half* __restrict__ Ol)
{
    const int bh = blockIdx.x;
    const int b = bh >> 4;
    const int h = bh & 15;

    __shared__ float qs[SEQ][DK];
    __shared__ float ks[SEQ][DK + 1];
    __shared__ float vs[SEQ][DK];
    __shared__ float sc[SEQ][SEQ];

    const int tid = threadIdx.x;
    for (int e = tid; e < SEQ * DK; e += 256) {
        const int s = e >> 6;
        const int d = e & 63;
        const size_t gidx = (size_t)(b * SEQ + s) * DMODEL + h * DK + d;
        qs[s][d] = Q[gidx];
        ks[s][d] = K[gidx];
        vs[s][d] = V[gidx];
    }
    __syncthreads();

    for (int e = tid; e < SEQ * SEQ; e += 256) {
        const int i = e / SEQ;
        const int j = e % SEQ;
        float acc = 0.f;
#pragma unroll
        for (int d = 0; d < DK; d++) acc = fmaf(qs[i][d], ks[j][d], acc);
        sc[i][j] = acc * 0.125f;
    }
    __syncthreads();

    if (tid < SEQ) {
        float mx = -1e30f;
#pragma unroll 1
        for (int j = 0; j < SEQ; j++) mx = fmaxf(mx, sc[tid][j]);
        float sum = 0.f;
#pragma unroll 1
        for (int j = 0; j < SEQ; j++) {
            float ev = expf(sc[tid][j] - mx);
            sum += ev;
            sc[tid][j] = ev;
        }
        const float r = 1.f / sum;
#pragma unroll 1
        for (int j = 0; j < SEQ; j++) sc[tid][j] *= r;
    }
    __syncthreads();

    for (int e = tid; e < SEQ * DK; e += 256) {
        const int i = e >> 6;
        const int d = e & 63;
        float acc = 0.f;
#pragma unroll
        for (int j = 0; j < SEQ; j++) acc = fmaf(sc[i][j], vs[j][d], acc);
        const size_t gidx = (size_t)(b * SEQ + i) * DMODEL + h * DK + d;
        __half hh, ll; split_f16(acc, hh, ll);
        Oh[gidx] = hh;
        Ol[gidx] = ll;
    }
}

// ---------------- fp32 SGEMM (head only) ----------------
#define BM 128
#define BN 128
#define BK 8
#define TM 8
#define TN 8
__global__ void __launch_bounds__(256) sgemm_kernel(
    const float* __restrict__ A, const float* __restrict__ B,
    const float* __restrict__ bias, float* __restrict__ C,
    int M, int N, int K, int relu)
{
    __shared__ float As[BK][BM];
    __shared__ float Bs[BK][BN];
    const int tid = threadIdx.x;
    const int m0 = blockIdx.y * BM;
    const int n0 = blockIdx.x * BN;
    const int arow = tid >> 1;
    const int acol = (tid & 1) * 4;
    const int brow = tid >> 5;
    const int bcol = (tid & 31) * 4;
    const float* Aptr = A + (size_t)(m0 + arow) * K + acol;
    const float* Bptr = B + (size_t)brow * N + n0 + bcol;
    const int tx = tid & 15;
    const int ty = tid >> 4;
    float acc[TM][TN];
#pragma unroll
    for (int i = 0; i < TM; i++)
#pragma unroll
        for (int j = 0; j < TN; j++) acc[i][j] = 0.f;
    for (int k0 = 0; k0 < K; k0 += BK) {
        float4 a4 = *reinterpret_cast<const float4*>(Aptr + k0);
        float4 b4 = *reinterpret_cast<const float4*>(Bptr + (size_t)k0 * N);
        As[acol + 0][arow] = a4.x;
        As[acol + 1][arow] = a4.y;
        As[acol + 2][arow] = a4.z;
        As[acol + 3][arow] = a4.w;
        *reinterpret_cast<float4*>(&Bs[brow][bcol]) = b4;
        __syncthreads();
#pragma unroll
        for (int k = 0; k < BK; k++) {
            float ra[TM], rb[TN];
            *reinterpret_cast<float4*>(&ra[0]) = *reinterpret_cast<const float4*>(&As[k][ty * TM]);
            *reinterpret_cast<float4*>(&ra[4]) = *reinterpret_cast<const float4*>(&As[k][ty * TM + 4]);
            *reinterpret_cast<float4*>(&rb[0]) = *reinterpret_cast<const float4*>(&Bs[k][tx * TN]);
            *reinterpret_cast<float4*>(&rb[4]) = *reinterpret_cast<const float4*>(&Bs[k][tx * TN + 4]);
#pragma unroll
            for (int i = 0; i < TM; i++)
#pragma unroll
                for (int j = 0; j < TN; j++)
                    acc[i][j] = fmaf(ra[i], rb[j], acc[i][j]);
        }
        __syncthreads();
    }
#pragma unroll
    for (int i = 0; i < TM; i++) {
        const size_t base = (size_t)(m0 + ty * TM + i) * N + n0 + tx * TN;
#pragma unroll
        for (int j = 0; j < TN; j++) {
            float v = acc[i][j] + __ldg(&bias[n0 + tx * TN + j]);
            if (relu) v = fmaxf(v, 0.f);
            C[base + j] = v;
        }
    }
}

// ---------------- head kernels ----------------
__global__ void __launch_bounds__(256) pool_ln_scale_kernel(
    const float* __restrict__ hbuf,
    const float* __restrict__ fin_g, const float* __restrict__ fin_b,
    const float* __restrict__ bn_g, const float* __restrict__ bn_b,
    float* __restrict__ z)
{
    const int bb = blockIdx.x;
    const float* x = hbuf + (size_t)(bb * SEQ + (SEQ - 1)) * DMODEL;
    float vals[4];
    float s = 0.f, s2 = 0.f;
#pragma unroll
    for (int i = 0; i < 4; i++) {
        float v = x[threadIdx.x + i * 256];
        vals[i] = v; s += v; s2 += v * v;
    }
#pragma unroll
    for (int o = 16; o; o >>= 1) {
        s  += __shfl_xor_sync(0xffffffffu, s, o);
        s2 += __shfl_xor_sync(0xffffffffu, s2, o);
    }
    __shared__ float sh[2][8];
    const int w = threadIdx.x >> 5;
    if ((threadIdx.x & 31) == 0) { sh[0][w] = s; sh[1][w] = s2; }
    __syncthreads();
    if (threadIdx.x < 32) {
        s  = (threadIdx.x < 8) ? sh[0][threadIdx.x] : 0.f;
        s2 = (threadIdx.x < 8) ? sh[1][threadIdx.x] : 0.f;
#pragma unroll
        for (int o = 4; o; o >>= 1) {
            s  += __shfl_xor_sync(0xffffffffu, s, o);
            s2 += __shfl_xor_sync(0xffffffffu, s2, o);
        }
        if (threadIdx.x == 0) { sh[0][0] = s; sh[1][0] = s2; }
    }
    __syncthreads();
    const float mean = sh[0][0] * (1.f / (float)DMODEL);
    float var = (sh[1][0] - (float)DMODEL * mean * mean) * (1.f / (float)(DMODEL - 1));
    var = fmaxf(var, 0.f);
    const float inv = 1.f / (sqrtf(var) + 1e-6f);
    const float invbn = 1.f / sqrtf(1.0f + 1e-5f);
#pragma unroll
    for (int i = 0; i < 4; i++) {
        const int c = threadIdx.x + i * 256;
        const float lnv = fin_g[c] * (vals[i] - mean) * inv + fin_b[c];
        z[(size_t)bb * DMODEL + c] = lnv * invbn * bn_g[c] + bn_b[c];
    }
}

__global__ void __launch_bounds__(256) bn2_kernel(
    const float* __restrict__ in, const float* __restrict__ g,
    const float* __restrict__ b, float* __restrict__ out)
{
    const int idx = blockIdx.x * 256 + threadIdx.x;
    const int c = idx & (DMODEL - 1);
    const float invbn = 1.f / sqrtf(1.0f + 1e-5f);
    out[idx] = in[idx] * invbn * g[c] + b[c];
}

__global__ void __launch_bounds__(128) fc_kernel(
    const float* __restrict__ z, const float* __restrict__ W,
    const float* __restrict__ bias, float* __restrict__ out)
{
    __shared__ float zs[DMODEL];
    const int bb = blockIdx.x;
    for (int i = threadIdx.x; i < DMODEL; i += 128) zs[i] = z[(size_t)bb * DMODEL + i];
    __syncthreads();
    const int c = threadIdx.x;
    if (c < NCLS) {
        float acc = bias[c];
        for (int k = 0; k < DMODEL; k++) acc = fmaf(zs[k], W[(size_t)k * NCLS + c], acc);
        out[(size_t)bb * NCLS + c] = acc;
    }
}

// ---------------- host launcher ----------------
static inline void launch_tgemm(const __half* Ah, const __half* Al,
                                const __half* Bh, const __half* Bl,
                                const float* bias, const float* resid,
                                float* Cf, __half* Chi, __half* Clo,
                                int M, int N, int Kp, int epi)
{
    dim3 grid(N / GBN, M / GBM);
    tgemm_kernel<<<grid, 256, TG_SMEM>>>(Ah, Al, Bh, Bl, bias, resid, Cf, Chi, Clo, Kp, N, epi);
}

extern "C" void kernel_launch(void* const* d_in, const int* in_sizes, int n_in,
                              void* d_out, int out_size)
{
    const float* x        = (const float*)d_in[0];
    const float* embed_w  = (const float*)d_in[1];
    const float* attn_w   = (const float*)d_in[2];
    const float* attn_b   = (const float*)d_in[3];
    const float* ff_w1    = (const float*)d_in[4];
    const float* ff_b1    = (const float*)d_in[5];
    const float* ff_w2    = (const float*)d_in[6];
    const float* ff_b2    = (const float*)d_in[7];
    const float* ln_g     = (const float*)d_in[8];
    const float* ln_b     = (const float*)d_in[9];
    const float* fin_g    = (const float*)d_in[10];
    const float* fin_b    = (const float*)d_in[11];
    const float* cf_bn_g  = (const float*)d_in[12];
    const float* cf_bn_b  = (const float*)d_in[13];
    const float* cf_w     = (const float*)d_in[14];
    const float* cf_b     = (const float*)d_in[15];
    const float* fc_bn_g  = (const float*)d_in[16];
    const float* fc_bn_b  = (const float*)d_in[17];
    const float* fc_w     = (const float*)d_in[18];
    const float* fc_b     = (const float*)d_in[19];

    cudaFuncSetAttribute(tgemm_kernel, cudaFuncAttributeMaxDynamicSharedMemorySize, TG_SMEM);

    float *g_h, *g_q, *g_k, *g_v, *g_z0, *g_z1;
    __half *g_xh, *g_xl, *g_ah, *g_al, *g_oh, *g_ol, *g_fh, *g_fl, *g_wth, *g_wtl;
    cudaGetSymbolAddress((void**)&g_h,  d_h);
    cudaGetSymbolAddress((void**)&g_q,  d_q);
    cudaGetSymbolAddress((void**)&g_k,  d_k);
    cudaGetSymbolAddress((void**)&g_v,  d_v);
    cudaGetSymbolAddress((void**)&g_z0, d_z0);
    cudaGetSymbolAddress((void**)&g_z1, d_z1);
    cudaGetSymbolAddress((void**)&g_xh, d_xh);
    cudaGetSymbolAddress((void**)&g_xl, d_xl);
    cudaGetSymbolAddress((void**)&g_ah, d_ah);
    cudaGetSymbolAddress((void**)&g_al, d_al);
    cudaGetSymbolAddress((void**)&g_oh, d_oh);
    cudaGetSymbolAddress((void**)&g_ol, d_ol);
    cudaGetSymbolAddress((void**)&g_fh, d_fh);
    cudaGetSymbolAddress((void**)&g_fl, d_fl);
    cudaGetSymbolAddress((void**)&g_wth, d_wth);
    cudaGetSymbolAddress((void**)&g_wtl, d_wtl);

    // ---- conversions ----
    cvt_x_kernel<<<(NTOK * KEMBP + 255) / 256, 256>>>(x, g_xh, g_xl);
    {
        dim3 blk(32, 8);
        cvt_wT_kernel<<<dim3(1024 / 32, KEMBP / 32), blk>>>(embed_w, g_wth, g_wtl, KEMB, DMODEL, KEMBP);
        for (int l = 0; l < NLAYER; l++) {
            const size_t lw = (size_t)WT_EMB_SZ + (size_t)l * WT_LAYER;
            const float* w = attn_w + (size_t)l * 4 * DMODEL * DMODEL;
            for (int i = 0; i < 4; i++) {
                cvt_wT_kernel<<<dim3(32, 32), blk>>>(
                    w + (size_t)i * DMODEL * DMODEL,
                    g_wth + lw + (size_t)i * DMODEL * DMODEL,
                    g_wtl + lw + (size_t)i * DMODEL * DMODEL,
                    DMODEL, DMODEL, DMODEL);
            }
            cvt_wT_kernel<<<dim3(DFF / 32, 32), blk>>>(
                ff_w1 + (size_t)l * DMODEL * DFF,
                g_wth + lw + 4u * 1048576u, g_wtl + lw + 4u * 1048576u,
                DMODEL, DFF, DMODEL);
            cvt_wT_kernel<<<dim3(32, DFF / 32), blk>>>(
                ff_w2 + (size_t)l * DFF * DMODEL,
                g_wth + lw + 8u * 1048576u, g_wtl + lw + 8u * 1048576u,
                DFF, DMODEL, DFF);
        }
    }

    // ---- embed: h = X @ embed_w + PE ----
    launch_tgemm(g_xh, g_xl, g_wth, g_wtl, nullptr, nullptr,
                 g_h, nullptr, nullptr, NTOK, DMODEL, KEMBP, 3);

    for (int l = 0; l < NLAYER; l++) {
        const size_t lw = (size_t)WT_EMB_SZ + (size_t)l * WT_LAYER;
        const __half* wq_h = g_wth + lw;
        const __half* wq_l = g_wtl + lw;
        const float* bq = attn_b + (size_t)l * 4 * DMODEL;

        ln_kernel<<<NTOK, 256>>>(g_h, ln_g + (size_t)(l * 2) * DMODEL,
                                 ln_b + (size_t)(l * 2) * DMODEL, g_ah, g_al);
        launch_tgemm(g_ah, g_al, wq_h + 0u * 1048576u, wq_l + 0u * 1048576u,
                     bq + 0 * DMODEL, nullptr, g_q, nullptr, nullptr, NTOK, DMODEL, DMODEL, 0);
        launch_tgemm(g_ah, g_al, wq_h + 1u * 1048576u, wq_l + 1u * 1048576u,
                     bq + 1 * DMODEL, nullptr, g_k, nullptr, nullptr, NTOK, DMODEL, DMODEL, 0);
        launch_tgemm(g_ah, g_al, wq_h + 2u * 1048576u, wq_l + 2u * 1048576u,
                     bq + 2 * DMODEL, nullptr, g_v, nullptr, nullptr, NTOK, DMODEL, DMODEL, 0);
        attn_kernel<<<BATCH * NHEAD, 256>>>(g_q, g_k, g_v, g_oh, g_ol);
        launch_tgemm(g_oh, g_ol, wq_h + 3u * 1048576u, wq_l + 3u * 1048576u,
                     bq + 3 * DMODEL, g_h, g_h, nullptr, nullptr, NTOK, DMODEL, DMODEL, 2);
        ln_kernel<<<NTOK, 256>>>(g_h, ln_g + (size_t)(l * 2 + 1) * DMODEL,
                                 ln_b + (size_t)(l * 2 + 1) * DMODEL, g_ah, g_al);
        launch_tgemm(g_ah, g_al, g_wth + lw + 4u * 1048576u, g_wtl + lw + 4u * 1048576u,
                     ff_b1 + (size_t)l * DFF, nullptr, nullptr, g_fh, g_fl, NTOK, DFF, DMODEL, 1);
        launch_tgemm(g_fh, g_fl, g_wth + lw + 8u * 1048576u, g_wtl + lw + 8u * 1048576u,
                     ff_b2 + (size_t)l * DMODEL, g_h, g_h, nullptr, nullptr, NTOK, DMODEL, DFF, 2);
    }

    // ---- classifier head ----
    pool_ln_scale_kernel<<<BATCH, 256>>>(g_h, fin_g, fin_b, cf_bn_g, cf_bn_b, g_z0);
    sgemm_kernel<<<dim3(DMODEL / BN, 1), 256>>>(g_z0, cf_w, cf_b, g_z1, BATCH, DMODEL, DMODEL, 1);
    bn2_kernel<<<(BATCH * DMODEL) / 256, 256>>>(g_z1, fc_bn_g, fc_bn_b, g_z0);
    fc_kernel<<<BATCH, 128>>>(g_z0, fc_w, fc_b, (float*)d_out);
}

// round 4
// speedup vs baseline: 3.6644x; 1.2339x over previous
#include <cuda_runtime.h>
#include <cuda_fp16.h>
#include <math.h>
#include <stdint.h>

// ---------------- problem constants ----------------
#define BATCH 128
#define SEQ   50
#define DMODEL 1024
#define DFF   4096
#define NHEAD 16
#define DK    64
#define NLAYER 5
#define KEMB  1200
#define KEMBP 1216
#define NTOK  6400
#define NCLS  71
#define NQKV  3072

// ---------------- HMMA GEMM tile config ----------------
#define GBM 128
#define GBN 128
#define GBK 32
#define OFF_AH 0
#define OFF_AL 8192
#define OFF_BH 16384
#define OFF_BL 24576
#define STAGE_BYTES 32768
#define NSTAGE 3
#define TG_SMEM (NSTAGE * STAGE_BYTES)   // 98304

// ---------------- weight scratch layout (transposed fp16 hi/lo) ----------------
#define WT_EMB_SZ (1024u*1216u)
#define WT_LAYER  (12u*1024u*1024u)
#define WT_TOTAL  (WT_EMB_SZ + 5u*WT_LAYER)

// ---------------- scratch (device globals) ----------------
__device__ float d_h  [NTOK * DMODEL];
__device__ float d_qkv[NTOK * NQKV];
__device__ float d_z0 [BATCH * DMODEL];
__device__ float d_z1 [BATCH * DMODEL];

__device__ __align__(16) __half d_xh[NTOK * KEMBP];
__device__ __align__(16) __half d_xl[NTOK * KEMBP];
__device__ __align__(16) __half d_ah[NTOK * DMODEL];
__device__ __align__(16) __half d_al[NTOK * DMODEL];
__device__ __align__(16) __half d_oh[NTOK * DMODEL];
__device__ __align__(16) __half d_ol[NTOK * DMODEL];
__device__ __align__(16) __half d_fh[NTOK * DFF];
__device__ __align__(16) __half d_fl[NTOK * DFF];
__device__ __align__(16) __half d_wth[WT_TOTAL];
__device__ __align__(16) __half d_wtl[WT_TOTAL];

// ---------------- PTX helpers ----------------
__device__ __forceinline__ uint32_t smem_u32(const void* p) {
    uint32_t a;
    asm("{ .reg .u64 t; cvta.to.shared.u64 t, %1; cvt.u32.u64 %0, t; }" : "=r"(a) : "l"(p));
    return a;
}
__device__ __forceinline__ void cpa16(uint32_t dst, const void* src) {
    asm volatile("cp.async.cg.shared.global [%0], [%1], 16;" :: "r"(dst), "l"(src));
}
#define CP_COMMIT() asm volatile("cp.async.commit_group;" ::: "memory")
#define CP_WAIT1()  asm volatile("cp.async.wait_group 1;" ::: "memory")
#define CP_WAIT0()  asm volatile("cp.async.wait_group 0;" ::: "memory")
#define LDSM4(r, a) \
    asm volatile("ldmatrix.sync.aligned.m8n8.x4.shared.b16 {%0,%1,%2,%3}, [%4];" \
        : "=r"((r)[0]), "=r"((r)[1]), "=r"((r)[2]), "=r"((r)[3]) : "r"(a))
#define MMA16816(c, a, b) \
    asm volatile("mma.sync.aligned.m16n8k16.row.col.f32.f16.f16.f32 " \
        "{%0,%1,%2,%3}, {%4,%5,%6,%7}, {%8,%9}, {%0,%1,%2,%3};" \
        : "+f"((c)[0]), "+f"((c)[1]), "+f"((c)[2]), "+f"((c)[3]) \
        : "r"((a)[0]), "r"((a)[1]), "r"((a)[2]), "r"((a)[3]), "r"((b)[0]), "r"((b)[1]))

__device__ __forceinline__ void split_f16(float v, __half& h, __half& l) {
    h = __float2half_rn(v);
    l = __float2half_rn(v - __half2float(h));
}

// ---------------- HMMA GEMM: C(MxN) = (Ah+Al) @ (Bh+Bl)^T, fp32 accum ----------------
// epi: 0 = +bias -> Cf; 1 = relu(+bias) -> Chi/Clo; 2 = +bias+resid -> Cf; 3 = +PE -> Cf
__global__ void __launch_bounds__(256, 2) tgemm_kernel(
    const __half* __restrict__ Ah, const __half* __restrict__ Al,
    const __half* __restrict__ Bh, const __half* __restrict__ Bl,
    const float* __restrict__ bias, const float* __restrict__ resid,
    float* __restrict__ Cf, __half* __restrict__ Chi, __half* __restrict__ Clo,
    int Kp, int N, int epi)
{
    extern __shared__ char sm[];
    const uint32_t smb = smem_u32(sm);
    const int tid  = threadIdx.x;
    const int lane = tid & 31;
    const int wid  = tid >> 5;
    const int wm   = wid & 3;      // warp m block (32 rows)
    const int wn   = wid >> 2;     // warp n block (64 cols)
    const int m0 = blockIdx.y * GBM;
    const int n0 = blockIdx.x * GBN;

    float acc[2][8][4];
#pragma unroll
    for (int i = 0; i < 2; i++)
#pragma unroll
        for (int j = 0; j < 8; j++)
#pragma unroll
            for (int t = 0; t < 4; t++) acc[i][j][t] = 0.f;

    auto load_stage = [&](int st, int k0) {
        const uint32_t sb = smb + (uint32_t)st * STAGE_BYTES;
#pragma unroll
        for (int i = 0; i < 2; i++) {
            const int id = tid + i * 256;          // 0..511
            const int row = id >> 2, cc = id & 3;
            const uint32_t off = (uint32_t)((row << 6) + ((cc ^ ((row >> 1) & 3)) << 4));
            const size_t ka = (size_t)(m0 + row) * Kp + k0 + cc * 8;
            const size_t kb = (size_t)(n0 + row) * Kp + k0 + cc * 8;
            cpa16(sb + OFF_AH + off, Ah + ka);
            cpa16(sb + OFF_AL + off, Al + ka);
            cpa16(sb + OFF_BH + off, Bh + kb);
            cpa16(sb + OFF_BL + off, Bl + kb);
        }
    };

    auto compute = [&](int st) {
        const uint32_t sb = smb + (uint32_t)st * STAGE_BYTES;
#pragma unroll
        for (int ks = 0; ks < 2; ks++) {
            uint32_t aH[2][4], aL[2][4];
#pragma unroll
            for (int mt = 0; mt < 2; mt++) {
                const int r = wm * 32 + mt * 16 + (lane & 15);
                const int ch = ks * 2 + (lane >> 4);
                const uint32_t off = (uint32_t)((r << 6) + ((ch ^ ((r >> 1) & 3)) << 4));
                LDSM4(aH[mt], sb + OFF_AH + off);
                LDSM4(aL[mt], sb + OFF_AL + off);
            }
#pragma unroll
            for (int half = 0; half < 2; half++) {
                uint32_t bH[4][2], bL[4][2];
#pragma unroll
                for (int p = 0; p < 2; p++) {
                    const int r = wn * 64 + (half * 2 + p) * 16 + (lane & 7) + ((lane & 16) >> 1);
                    const int ch = ks * 2 + ((lane >> 3) & 1);
                    const uint32_t off = (uint32_t)((r << 6) + ((ch ^ ((r >> 1) & 3)) << 4));
                    uint32_t q[4];
                    LDSM4(q, sb + OFF_BH + off);
                    bH[p*2][0] = q[0]; bH[p*2][1] = q[1];
                    bH[p*2+1][0] = q[2]; bH[p*2+1][1] = q[3];
                    LDSM4(q, sb + OFF_BL + off);
                    bL[p*2][0] = q[0]; bL[p*2][1] = q[1];
                    bL[p*2+1][0] = q[2]; bL[p*2+1][1] = q[3];
                }
#pragma unroll
                for (int mt = 0; mt < 2; mt++)
#pragma unroll
                    for (int nt = 0; nt < 4; nt++) MMA16816(acc[mt][half*4+nt], aH[mt], bH[nt]);
#pragma unroll
                for (int mt = 0; mt < 2; mt++)
#pragma unroll
                    for (int nt = 0; nt < 4; nt++) MMA16816(acc[mt][half*4+nt], aH[mt], bL[nt]);
#pragma unroll
                for (int mt = 0; mt < 2; mt++)
#pragma unroll
                    for (int nt = 0; nt < 4; nt++) MMA16816(acc[mt][half*4+nt], aL[mt], bH[nt]);
            }
        }
    };

    const int nchunk = Kp / GBK;
    load_stage(0, 0);
    CP_COMMIT();
    if (nchunk > 1) { load_stage(1, GBK); CP_COMMIT(); }
    int s_c = 0, s_ld = 2;
    for (int c = 0; c < nchunk; c++) {
        if (c + 1 < nchunk) CP_WAIT1(); else CP_WAIT0();
        __syncthreads();   // stage c ready; all warps done with compute(c-1)
        if (c + 2 < nchunk) { load_stage(s_ld, (c + 2) * GBK); CP_COMMIT(); }
        compute(s_c);
        s_c = (s_c == 2) ? 0 : s_c + 1;
        s_ld = (s_ld == 2) ? 0 : s_ld + 1;
    }

    // ---------------- epilogue ----------------
#pragma unroll
    for (int mt = 0; mt < 2; mt++) {
        const int r0 = m0 + wm * 32 + mt * 16 + (lane >> 2);
#pragma unroll
        for (int nt = 0; nt < 8; nt++) {
            const int col = n0 + wn * 64 + nt * 8 + (lane & 3) * 2;
            const float* a = acc[mt][nt];
            if (epi == 1) {
                const float b0 = __ldg(&bias[col]);
                const float b1 = __ldg(&bias[col + 1]);
#pragma unroll
                for (int rr = 0; rr < 2; rr++) {
                    const int row = r0 + rr * 8;
                    const float v0 = fmaxf(a[rr * 2 + 0] + b0, 0.f);
                    const float v1 = fmaxf(a[rr * 2 + 1] + b1, 0.f);
                    __half h0, l0, h1, l1;
                    split_f16(v0, h0, l0);
                    split_f16(v1, h1, l1);
                    *reinterpret_cast<__half2*>(&Chi[(size_t)row * N + col]) = __halves2half2(h0, h1);
                    *reinterpret_cast<__half2*>(&Clo[(size_t)row * N + col]) = __halves2half2(l0, l1);
                }
            } else if (epi == 3) {
                const float dv = expf((float)(col & ~1) * (-9.210340371976184f / (float)DMODEL));
#pragma unroll
                for (int rr = 0; rr < 2; rr++) {
                    const int row = r0 + rr * 8;
                    const int srow = row % SEQ;
                    float sn, cs;
                    sincosf((float)srow * dv, &sn, &cs);
                    float2 o;
                    o.x = a[rr * 2 + 0] + sn;
                    o.y = a[rr * 2 + 1] + cs;
                    *reinterpret_cast<float2*>(&Cf[(size_t)row * N + col]) = o;
                }
            } else {
                const float b0 = __ldg(&bias[col]);
                const float b1 = __ldg(&bias[col + 1]);
#pragma unroll
                for (int rr = 0; rr < 2; rr++) {
                    const int row = r0 + rr * 8;
                    float v0 = a[rr * 2 + 0] + b0;
                    float v1 = a[rr * 2 + 1] + b1;
                    if (epi == 2) {
                        const float2 rv = *reinterpret_cast<const float2*>(&resid[(size_t)row * N + col]);
                        v0 += rv.x; v1 += rv.y;
                    }
                    float2 o; o.x = v0; o.y = v1;
                    *reinterpret_cast<float2*>(&Cf[(size_t)row * N + col]) = o;
                }
            }
        }
    }
}

// ---------------- converters ----------------
__global__ void __launch_bounds__(256) cvt_x_kernel(
    const float* __restrict__ x, __half* __restrict__ xh, __half* __restrict__ xl)
{
    const int idx = blockIdx.x * 256 + threadIdx.x;
    if (idx >= NTOK * KEMBP) return;
    const int r = idx / KEMBP, c = idx % KEMBP;
    const float v = (c < KEMB) ? x[(size_t)r * KEMB + c] : 0.f;
    __half h, l; split_f16(v, h, l);
    xh[idx] = h; xl[idx] = l;
}

// W [K][N] fp32 -> transposed, split, padded: Th/Tl [N][Kp] fp16
__global__ void cvt_wT_kernel(
    const float* __restrict__ W, __half* __restrict__ Th, __half* __restrict__ Tl,
    int K, int N, int Kp)
{
    __shared__ float t[32][33];
    const int k0 = blockIdx.y * 32, n0 = blockIdx.x * 32;
    const int tx = threadIdx.x, ty = threadIdx.y;   // block (32, 8)
#pragma unroll
    for (int i = 0; i < 32; i += 8) {
        const int k = k0 + ty + i;
        t[ty + i][tx] = (k < K) ? W[(size_t)k * N + n0 + tx] : 0.f;
    }
    __syncthreads();
#pragma unroll
    for (int i = 0; i < 32; i += 8) {
        const int n = n0 + ty + i;
        const int k = k0 + tx;
        __half h, l; split_f16(t[tx][ty + i], h, l);
        Th[(size_t)n * Kp + k] = h;
        Tl[(size_t)n * Kp + k] = l;
    }
}

// ---------------- LayerNorm (ddof=1, eps on std) -> fp16 hi/lo ----------------
__global__ void __launch_bounds__(256) ln_kernel(
    const float* __restrict__ in, const float* __restrict__ g,
    const float* __restrict__ b, __half* __restrict__ outh, __half* __restrict__ outl)
{
    const int row = blockIdx.x;
    const float* x = in + (size_t)row * DMODEL;
    float vals[4];
    float s = 0.f, s2 = 0.f;
#pragma unroll
    for (int i = 0; i < 4; i++) {
        float v = x[threadIdx.x + i * 256];
        vals[i] = v; s += v; s2 += v * v;
    }
#pragma unroll
    for (int o = 16; o; o >>= 1) {
        s  += __shfl_xor_sync(0xffffffffu, s, o);
        s2 += __shfl_xor_sync(0xffffffffu, s2, o);
    }
    __shared__ float sh[2][8];
    const int w = threadIdx.x >> 5;
    if ((threadIdx.x & 31) == 0) { sh[0][w] = s; sh[1][w] = s2; }
    __syncthreads();
    if (threadIdx.x < 32) {
        s  = (threadIdx.x < 8) ? sh[0][threadIdx.x] : 0.f;
        s2 = (threadIdx.x < 8) ? sh[1][threadIdx.x] : 0.f;
#pragma unroll
        for (int o = 4; o; o >>= 1) {
            s  += __shfl_xor_sync(0xffffffffu, s, o);
            s2 += __shfl_xor_sync(0xffffffffu, s2, o);
        }
        if (threadIdx.x == 0) { sh[0][0] = s; sh[1][0] = s2; }
    }
    __syncthreads();
    const float mean = sh[0][0] * (1.f / (float)DMODEL);
    float var = (sh[1][0] - (float)DMODEL * mean * mean) * (1.f / (float)(DMODEL - 1));
    var = fmaxf(var, 0.f);
    const float inv = 1.f / (sqrtf(var) + 1e-6f);
#pragma unroll
    for (int i = 0; i < 4; i++) {
        const int c = threadIdx.x + i * 256;
        const float r = g[c] * (vals[i] - mean) * inv + b[c];
        __half h, l; split_f16(r, h, l);
        outh[(size_t)row * DMODEL + c] = h;
        outl[(size_t)row * DMODEL + c] = l;
    }
}

// ---------------- attention on fused QKV buffer: one block per (b, h) ----------------
__global__ void __launch_bounds__(256) attn_kernel(
    const float* __restrict__ QKV, __half* __restrict__ Oh, __half* __restrict__ Ol)
{
    const int bh = blockIdx.x;
    const int b = bh >> 4;
    const int h = bh & 15;

    __shared__ float qs[SEQ][DK];
    __shared__ float ks[SEQ][DK + 1];
    __shared__ float vs[SEQ][DK];
    __shared__ float sc[SEQ][SEQ];

    const int tid = threadIdx.x;
    for (int e = tid; e < SEQ * DK; e += 256) {
        const int s = e >> 6;
        const int d = e & 63;
        const size_t gbase = (size_t)(b * SEQ + s) * NQKV + h * DK + d;
        qs[s][d] = QKV[gbase];
        ks[s][d] = QKV[gbase + DMODEL];
        vs[s][d] = QKV[gbase + 2 * DMODEL];
    }
    __syncthreads();

    for (int e = tid; e < SEQ * SEQ; e += 256) {
        const int i = e / SEQ;
        const int j = e % SEQ;
        float acc = 0.f;
#pragma unroll
        for (int d = 0; d < DK; d++) acc = fmaf(qs[i][d], ks[j][d], acc);
        sc[i][j] = acc * 0.125f;
    }
    __syncthreads();

    if (tid < SEQ) {
        float mx = -1e30f;
#pragma unroll 1
        for (int j = 0; j < SEQ; j++) mx = fmaxf(mx, sc[tid][j]);
        float sum = 0.f;
#pragma unroll 1
        for (int j = 0; j < SEQ; j++) {
            float ev = expf(sc[tid][j] - mx);
            sum += ev;
            sc[tid][j] = ev;
        }
        const float r = 1.f / sum;
#pragma unroll 1
        for (int j = 0; j < SEQ; j++) sc[tid][j] *= r;
    }
    __syncthreads();

    for (int e = tid; e < SEQ * DK; e += 256) {
        const int i = e >> 6;
        const int d = e & 63;
        float acc = 0.f;
#pragma unroll
        for (int j = 0; j < SEQ; j++) acc = fmaf(sc[i][j], vs[j][d], acc);
        const size_t gidx = (size_t)(b * SEQ + i) * DMODEL + h * DK + d;
        __half hh, ll; split_f16(acc, hh, ll);
        Oh[gidx] = hh;
        Ol[gidx] = ll;
    }
}

// ---------------- fp32 SGEMM (head only) ----------------
#define BM 128
#define BN 128
#define BK 8
#define TM 8
#define TN 8
__global__ void __launch_bounds__(256) sgemm_kernel(
    const float* __restrict__ A, const float* __restrict__ B,
    const float* __restrict__ bias, float* __restrict__ C,
    int M, int N, int K, int relu)
{
    __shared__ float As[BK][BM];
    __shared__ float Bs[BK][BN];
    const int tid = threadIdx.x;
    const int m0 = blockIdx.y * BM;
    const int n0 = blockIdx.x * BN;
    const int arow = tid >> 1;
    const int acol = (tid & 1) * 4;
    const int brow = tid >> 5;
    const int bcol = (tid & 31) * 4;
    const float* Aptr = A + (size_t)(m0 + arow) * K + acol;
    const float* Bptr = B + (size_t)brow * N + n0 + bcol;
    const int tx = tid & 15;
    const int ty = tid >> 4;
    float acc[TM][TN];
#pragma unroll
    for (int i = 0; i < TM; i++)
#pragma unroll
        for (int j = 0; j < TN; j++) acc[i][j] = 0.f;
    for (int k0 = 0; k0 < K; k0 += BK) {
        float4 a4 = *reinterpret_cast<const float4*>(Aptr + k0);
        float4 b4 = *reinterpret_cast<const float4*>(Bptr + (size_t)k0 * N);
        As[acol + 0][arow] = a4.x;
        As[acol + 1][arow] = a4.y;
        As[acol + 2][arow] = a4.z;
        As[acol + 3][arow] = a4.w;
        *reinterpret_cast<float4*>(&Bs[brow][bcol]) = b4;
        __syncthreads();
#pragma unroll
        for (int k = 0; k < BK; k++) {
            float ra[TM], rb[TN];
            *reinterpret_cast<float4*>(&ra[0]) = *reinterpret_cast<const float4*>(&As[k][ty * TM]);
            *reinterpret_cast<float4*>(&ra[4]) = *reinterpret_cast<const float4*>(&As[k][ty * TM + 4]);
            *reinterpret_cast<float4*>(&rb[0]) = *reinterpret_cast<const float4*>(&Bs[k][tx * TN]);
            *reinterpret_cast<float4*>(&rb[4]) = *reinterpret_cast<const float4*>(&Bs[k][tx * TN + 4]);
#pragma unroll
            for (int i = 0; i < TM; i++)
#pragma unroll
                for (int j = 0; j < TN; j++)
                    acc[i][j] = fmaf(ra[i], rb[j], acc[i][j]);
        }
        __syncthreads();
    }
#pragma unroll
    for (int i = 0; i < TM; i++) {
        const size_t base = (size_t)(m0 + ty * TM + i) * N + n0 + tx * TN;
#pragma unroll
        for (int j = 0; j < TN; j++) {
            float v = acc[i][j] + __ldg(&bias[n0 + tx * TN + j]);
            if (relu) v = fmaxf(v, 0.f);
            C[base + j] = v;
        }
    }
}

// ---------------- head kernels ----------------
__global__ void __launch_bounds__(256) pool_ln_scale_kernel(
    const float* __restrict__ hbuf,
    const float* __restrict__ fin_g, const float* __restrict__ fin_b,
    const float* __restrict__ bn_g, const float* __restrict__ bn_b,
    float* __restrict__ z)
{
    const int bb = blockIdx.x;
    const float* x = hbuf + (size_t)(bb * SEQ + (SEQ - 1)) * DMODEL;
    float vals[4];
    float s = 0.f, s2 = 0.f;
#pragma unroll
    for (int i = 0; i < 4; i++) {
        float v = x[threadIdx.x + i * 256];
        vals[i] = v; s += v; s2 += v * v;
    }
#pragma unroll
    for (int o = 16; o; o >>= 1) {
        s  += __shfl_xor_sync(0xffffffffu, s, o);
        s2 += __shfl_xor_sync(0xffffffffu, s2, o);
    }
    __shared__ float sh[2][8];
    const int w = threadIdx.x >> 5;
    if ((threadIdx.x & 31) == 0) { sh[0][w] = s; sh[1][w] = s2; }
    __syncthreads();
    if (threadIdx.x < 32) {
        s  = (threadIdx.x < 8) ? sh[0][threadIdx.x] : 0.f;
        s2 = (threadIdx.x < 8) ? sh[1][threadIdx.x] : 0.f;
#pragma unroll
        for (int o = 4; o; o >>= 1) {
            s  += __shfl_xor_sync(0xffffffffu, s, o);
            s2 += __shfl_xor_sync(0xffffffffu, s2, o);
        }
        if (threadIdx.x == 0) { sh[0][0] = s; sh[1][0] = s2; }
    }
    __syncthreads();
    const float mean = sh[0][0] * (1.f / (float)DMODEL);
    float var = (sh[1][0] - (float)DMODEL * mean * mean) * (1.f / (float)(DMODEL - 1));
    var = fmaxf(var, 0.f);
    const float inv = 1.f / (sqrtf(var) + 1e-6f);
    const float invbn = 1.f / sqrtf(1.0f + 1e-5f);
#pragma unroll
    for (int i = 0; i < 4; i++) {
        const int c = threadIdx.x + i * 256;
        const float lnv = fin_g[c] * (vals[i] - mean) * inv + fin_b[c];
        z[(size_t)bb * DMODEL + c] = lnv * invbn * bn_g[c] + bn_b[c];
    }
}

__global__ void __launch_bounds__(256) bn2_kernel(
    const float* __restrict__ in, const float* __restrict__ g,
    const float* __restrict__ b, float* __restrict__ out)
{
    const int idx = blockIdx.x * 256 + threadIdx.x;
    const int c = idx & (DMODEL - 1);
    const float invbn = 1.f / sqrtf(1.0f + 1e-5f);
    out[idx] = in[idx] * invbn * g[c] + b[c];
}

__global__ void __launch_bounds__(128) fc_kernel(
    const float* __restrict__ z, const float* __restrict__ W,
    const float* __restrict__ bias, float* __restrict__ out)
{
    __shared__ float zs[DMODEL];
    const int bb = blockIdx.x;
    for (int i = threadIdx.x; i < DMODEL; i += 128) zs[i] = z[(size_t)bb * DMODEL + i];
    __syncthreads();
    const int c = threadIdx.x;
    if (c < NCLS) {
        float acc = bias[c];
        for (int k = 0; k < DMODEL; k++) acc = fmaf(zs[k], W[(size_t)k * NCLS + c], acc);
        out[(size_t)bb * NCLS + c] = acc;
    }
}

// ---------------- host launcher ----------------
static inline void launch_tgemm(const __half* Ah, const __half* Al,
                                const __half* Bh, const __half* Bl,
                                const float* bias, const float* resid,
                                float* Cf, __half* Chi, __half* Clo,
                                int M, int N, int Kp, int epi)
{
    dim3 grid(N / GBN, M / GBM);
    tgemm_kernel<<<grid, 256, TG_SMEM>>>(Ah, Al, Bh, Bl, bias, resid, Cf, Chi, Clo, Kp, N, epi);
}

extern "C" void kernel_launch(void* const* d_in, const int* in_sizes, int n_in,
                              void* d_out, int out_size)
{
    const float* x        = (const float*)d_in[0];
    const float* embed_w  = (const float*)d_in[1];
    const float* attn_w   = (const float*)d_in[2];
    const float* attn_b   = (const float*)d_in[3];
    const float* ff_w1    = (const float*)d_in[4];
    const float* ff_b1    = (const float*)d_in[5];
    const float* ff_w2    = (const float*)d_in[6];
    const float* ff_b2    = (const float*)d_in[7];
    const float* ln_g     = (const float*)d_in[8];
    const float* ln_b     = (const float*)d_in[9];
    const float* fin_g    = (const float*)d_in[10];
    const float* fin_b    = (const float*)d_in[11];
    const float* cf_bn_g  = (const float*)d_in[12];
    const float* cf_bn_b  = (const float*)d_in[13];
    const float* cf_w     = (const float*)d_in[14];
    const float* cf_b     = (const float*)d_in[15];
    const float* fc_bn_g  = (const float*)d_in[16];
    const float* fc_bn_b  = (const float*)d_in[17];
    const float* fc_w     = (const float*)d_in[18];
    const float* fc_b     = (const float*)d_in[19];

    cudaFuncSetAttribute(tgemm_kernel, cudaFuncAttributeMaxDynamicSharedMemorySize, TG_SMEM);

    float *g_h, *g_qkv, *g_z0, *g_z1;
    __half *g_xh, *g_xl, *g_ah, *g_al, *g_oh, *g_ol, *g_fh, *g_fl, *g_wth, *g_wtl;
    cudaGetSymbolAddress((void**)&g_h,   d_h);
    cudaGetSymbolAddress((void**)&g_qkv, d_qkv);
    cudaGetSymbolAddress((void**)&g_z0,  d_z0);
    cudaGetSymbolAddress((void**)&g_z1,  d_z1);
    cudaGetSymbolAddress((void**)&g_xh,  d_xh);
    cudaGetSymbolAddress((void**)&g_xl,  d_xl);
    cudaGetSymbolAddress((void**)&g_ah,  d_ah);
    cudaGetSymbolAddress((void**)&g_al,  d_al);
    cudaGetSymbolAddress((void**)&g_oh,  d_oh);
    cudaGetSymbolAddress((void**)&g_ol,  d_ol);
    cudaGetSymbolAddress((void**)&g_fh,  d_fh);
    cudaGetSymbolAddress((void**)&g_fl,  d_fl);
    cudaGetSymbolAddress((void**)&g_wth, d_wth);
    cudaGetSymbolAddress((void**)&g_wtl, d_wtl);

    // ---- conversions ----
    cvt_x_kernel<<<(NTOK * KEMBP + 255) / 256, 256>>>(x, g_xh, g_xl);
    {
        dim3 blk(32, 8);
        cvt_wT_kernel<<<dim3(1024 / 32, KEMBP / 32), blk>>>(embed_w, g_wth, g_wtl, KEMB, DMODEL, KEMBP);
        for (int l = 0; l < NLAYER; l++) {
            const size_t lw = (size_t)WT_EMB_SZ + (size_t)l * WT_LAYER;
            const float* w = attn_w + (size_t)l * 4 * DMODEL * DMODEL;
            for (int i = 0; i < 4; i++) {
                cvt_wT_kernel<<<dim3(32, 32), blk>>>(
                    w + (size_t)i * DMODEL * DMODEL,
                    g_wth + lw + (size_t)i * DMODEL * DMODEL,
                    g_wtl + lw + (size_t)i * DMODEL * DMODEL,
                    DMODEL, DMODEL, DMODEL);
            }
            cvt_wT_kernel<<<dim3(DFF / 32, 32), blk>>>(
                ff_w1 + (size_t)l * DMODEL * DFF,
                g_wth + lw + 4u * 1048576u, g_wtl + lw + 4u * 1048576u,
                DMODEL, DFF, DMODEL);
            cvt_wT_kernel<<<dim3(32, DFF / 32), blk>>>(
                ff_w2 + (size_t)l * DFF * DMODEL,
                g_wth + lw + 8u * 1048576u, g_wtl + lw + 8u * 1048576u,
                DFF, DMODEL, DFF);
        }
    }

    // ---- embed: h = X @ embed_w + PE ----
    launch_tgemm(g_xh, g_xl, g_wth, g_wtl, nullptr, nullptr,
                 g_h, nullptr, nullptr, NTOK, DMODEL, KEMBP, 3);

    for (int l = 0; l < NLAYER; l++) {
        const size_t lw = (size_t)WT_EMB_SZ + (size_t)l * WT_LAYER;
        const __half* wq_h = g_wth + lw;
        const __half* wq_l = g_wtl + lw;
        const float* bq = attn_b + (size_t)l * 4 * DMODEL;

        ln_kernel<<<NTOK, 256>>>(g_h, ln_g + (size_t)(l * 2) * DMODEL,
                                 ln_b + (size_t)(l * 2) * DMODEL, g_ah, g_al);
        // fused QKV: B = [3072][1024] (wq,wk,wv transposed, contiguous); bias = bq[0..3071]
        launch_tgemm(g_ah, g_al, wq_h, wq_l, bq, nullptr,
                     g_qkv, nullptr, nullptr, NTOK, NQKV, DMODEL, 0);
        attn_kernel<<<BATCH * NHEAD, 256>>>(g_qkv, g_oh, g_ol);
        launch_tgemm(g_oh, g_ol, wq_h + 3u * 1048576u, wq_l + 3u * 1048576u,
                     bq + 3 * DMODEL, g_h, g_h, nullptr, nullptr, NTOK, DMODEL, DMODEL, 2);
        ln_kernel<<<NTOK, 256>>>(g_h, ln_g + (size_t)(l * 2 + 1) * DMODEL,
                                 ln_b + (size_t)(l * 2 + 1) * DMODEL, g_ah, g_al);
        launch_tgemm(g_ah, g_al, g_wth + lw + 4u * 1048576u, g_wtl + lw + 4u * 1048576u,
                     ff_b1 + (size_t)l * DFF, nullptr, nullptr, g_fh, g_fl, NTOK, DFF, DMODEL, 1);
        launch_tgemm(g_fh, g_fl, g_wth + lw + 8u * 1048576u, g_wtl + lw + 8u * 1048576u,
                     ff_b2 + (size_t)l * DMODEL, g_h, g_h, nullptr, nullptr, NTOK, DMODEL, DFF, 2);
    }

    // ---- classifier head ----
    pool_ln_scale_kernel<<<BATCH, 256>>>(g_h, fin_g, fin_b, cf_bn_g, cf_bn_b, g_z0);
    sgemm_kernel<<<dim3(DMODEL / BN, 1), 256>>>(g_z0, cf_w, cf_b, g_z1, BATCH, DMODEL, DMODEL, 1);
    bn2_kernel<<<(BATCH * DMODEL) / 256, 256>>>(g_z1, fc_bn_g, fc_bn_b, g_z0);
    fc_kernel<<<BATCH, 128>>>(g_z0, fc_w, fc_b, (float*)d_out);
}